// round 1
// baseline (speedup 1.0000x reference)
#include <cuda_runtime.h>
#include <math.h>

#define BB 2
#define SS 2048
#define DD 2048
#define HH 16
#define HD 128

// Scratch (device globals; no allocation allowed)
__device__ float g_q[BB * SS * DD];      // 64 MB
__device__ float g_k[BB * SS * HD];      // 2 MB
__device__ float g_v[BB * SS * HD];      // 2 MB
__device__ float g_att[BB * SS * DD];    // 64 MB

// ---------------------------------------------------------------------------
// C[M,N] = A[M,K] @ W[N,K]^T   (torch Linear convention)
// 64x64 block tile, BK=16, 256 threads, 4x4 micro-tile per thread.
// Requires M%64==0, N%64==0, K%16==0 (true for all shapes here).
// ---------------------------------------------------------------------------
__global__ void sgemm_nt(const float* __restrict__ A, const float* __restrict__ W,
                         float* __restrict__ C, int M, int N, int K) {
    const int BM = 64, BN = 64, BK = 16;
    __shared__ float As[BK][BM];
    __shared__ float Ws[BK][BN];

    const int tx = threadIdx.x & 15;
    const int ty = threadIdx.x >> 4;
    const int m0 = blockIdx.y * BM;
    const int n0 = blockIdx.x * BN;

    float acc[4][4];
#pragma unroll
    for (int i = 0; i < 4; ++i)
#pragma unroll
        for (int j = 0; j < 4; ++j) acc[i][j] = 0.f;

    const int t  = threadIdx.x;
    const int lm = t >> 2;          // 0..63 (row within tile)
    const int lk = (t & 3) * 4;     // 0,4,8,12

    for (int k0 = 0; k0 < K; k0 += BK) {
        float4 av = *(const float4*)&A[(size_t)(m0 + lm) * K + k0 + lk];
        float4 wv = *(const float4*)&W[(size_t)(n0 + lm) * K + k0 + lk];
        As[lk + 0][lm] = av.x; As[lk + 1][lm] = av.y;
        As[lk + 2][lm] = av.z; As[lk + 3][lm] = av.w;
        Ws[lk + 0][lm] = wv.x; Ws[lk + 1][lm] = wv.y;
        Ws[lk + 2][lm] = wv.z; Ws[lk + 3][lm] = wv.w;
        __syncthreads();

#pragma unroll
        for (int k = 0; k < BK; ++k) {
            float4 a4 = *(const float4*)&As[k][ty * 4];
            float4 b4 = *(const float4*)&Ws[k][tx * 4];
            float a[4] = {a4.x, a4.y, a4.z, a4.w};
            float b[4] = {b4.x, b4.y, b4.z, b4.w};
#pragma unroll
            for (int i = 0; i < 4; ++i)
#pragma unroll
                for (int j = 0; j < 4; ++j) acc[i][j] += a[i] * b[j];
        }
        __syncthreads();
    }

#pragma unroll
    for (int i = 0; i < 4; ++i) {
        float4 r = make_float4(acc[i][0], acc[i][1], acc[i][2], acc[i][3]);
        *(float4*)&C[(size_t)(m0 + ty * 4 + i) * N + n0 + tx * 4] = r;
    }
}

// ---------------------------------------------------------------------------
// In-place RoPE over tensor [B*S, rowsize] where rowsize is D (per-head 128)
// or HD. Pair (2*pc, 2*pc+1); within-head pair index i = pc % 64.
// ---------------------------------------------------------------------------
__global__ void rope_kernel(float* __restrict__ tns,
                            const float* __restrict__ cosT,
                            const float* __restrict__ sinT,
                            int rowsize, int npairs) {
    int p = blockIdx.x * blockDim.x + threadIdx.x;
    if (p >= npairs) return;
    const int hp  = rowsize >> 1;
    const int row = p / hp;
    const int pc  = p - row * hp;
    const int s   = row & (SS - 1);
    const int i   = pc & 63;
    const float c  = cosT[s * 64 + i];
    const float sn = sinT[s * 64 + i];
    float* base = tns + (size_t)row * rowsize + 2 * pc;
    const float x0 = base[0], x1 = base[1];
    base[0] = x0 * c - x1 * sn;
    base[1] = x0 * sn + x1 * c;
}

// ---------------------------------------------------------------------------
// Causal flash attention, fp32, MQA (single KV head).
// grid (S/32, H, B), 128 threads. Each quad of threads owns one query row;
// thread `sub` owns dims {sub, sub+4, ..., sub+124} (interleaved -> no smem
// bank conflicts: quad addresses are 4 consecutive words, rows broadcast).
// ---------------------------------------------------------------------------
__global__ void flash_kernel(const float* __restrict__ q,
                             const float* __restrict__ k,
                             const float* __restrict__ v,
                             float* __restrict__ out) {
    const int qb  = blockIdx.x;
    const int h   = blockIdx.y;
    const int b   = blockIdx.z;
    const int row = threadIdx.x >> 2;   // 0..31
    const int sub = threadIdx.x & 3;
    const int qi  = qb * 32 + row;

    __shared__ float Ks[32][HD];
    __shared__ float Vs[32][HD];

    float qf[32];
    const float* qrow = q + ((size_t)b * SS + qi) * DD + h * HD;
#pragma unroll
    for (int tt = 0; tt < 32; ++tt) qf[tt] = qrow[sub + 4 * tt];

    float o[32];
#pragma unroll
    for (int tt = 0; tt < 32; ++tt) o[tt] = 0.f;

    float m = -1e30f, l = 0.f;
    const float scale = 0.08838834764831845f;  // 1/sqrt(128)

    const int kend = qb * 32 + 32;  // exclusive
    for (int k0 = 0; k0 < kend; k0 += 32) {
        // Cooperative load of K/V tile [32,128] = 1024 float4 total.
        {
            const float4* kg = (const float4*)(k + ((size_t)b * SS + k0) * HD);
            const float4* vg = (const float4*)(v + ((size_t)b * SS + k0) * HD);
            float4* ks4 = (float4*)&Ks[0][0];
            float4* vs4 = (float4*)&Vs[0][0];
#pragma unroll
            for (int it = 0; it < 8; ++it) {
                int idx = threadIdx.x + it * 128;
                ks4[idx] = kg[idx];
                vs4[idx] = vg[idx];
            }
        }
        __syncthreads();

        float s[32];
#pragma unroll
        for (int kk = 0; kk < 32; ++kk) {
            float acc = 0.f;
#pragma unroll
            for (int tt = 0; tt < 32; ++tt) acc += qf[tt] * Ks[kk][sub + 4 * tt];
            s[kk] = acc;
        }
        // Reduce partial dots across the quad (full sum lands in all 4 lanes)
#pragma unroll
        for (int kk = 0; kk < 32; ++kk) {
            float t0 = s[kk];
            t0 += __shfl_xor_sync(0xffffffffu, t0, 1);
            t0 += __shfl_xor_sync(0xffffffffu, t0, 2);
            t0 *= scale;
            if (k0 + kk > qi) t0 = -1e30f;
            s[kk] = t0;
        }
        float tilem = -1e30f;
#pragma unroll
        for (int kk = 0; kk < 32; ++kk) tilem = fmaxf(tilem, s[kk]);
        const float mnew = fmaxf(m, tilem);
        const float corr = __expf(m - mnew);
        float ladd = 0.f;
#pragma unroll
        for (int kk = 0; kk < 32; ++kk) {
            s[kk] = __expf(s[kk] - mnew);
            ladd += s[kk];
        }
        l = l * corr + ladd;
        m = mnew;
#pragma unroll
        for (int tt = 0; tt < 32; ++tt) o[tt] *= corr;
#pragma unroll
        for (int kk = 0; kk < 32; ++kk) {
            const float p = s[kk];
#pragma unroll
            for (int tt = 0; tt < 32; ++tt) o[tt] += p * Vs[kk][sub + 4 * tt];
        }
        __syncthreads();
    }

    const float inv = 1.f / l;
    float* orow = out + ((size_t)b * SS + qi) * DD + h * HD;
#pragma unroll
    for (int tt = 0; tt < 32; ++tt) orow[sub + 4 * tt] = o[tt] * inv;
}

// ---------------------------------------------------------------------------
extern "C" void kernel_launch(void* const* d_in, const int* in_sizes, int n_in,
                              void* d_out, int out_size) {
    const float* x    = (const float*)d_in[0];
    const float* Wq   = (const float*)d_in[1];
    const float* Wk   = (const float*)d_in[2];
    const float* Wv   = (const float*)d_in[3];
    const float* Wo   = (const float*)d_in[4];
    const float* rcos = (const float*)d_in[5];
    const float* rsin = (const float*)d_in[6];
    float* out = (float*)d_out;

    float *q_p, *k_p, *v_p, *att_p;
    cudaGetSymbolAddress((void**)&q_p, g_q);
    cudaGetSymbolAddress((void**)&k_p, g_k);
    cudaGetSymbolAddress((void**)&v_p, g_v);
    cudaGetSymbolAddress((void**)&att_p, g_att);

    const int M = BB * SS;  // 4096

    // Q = x @ Wq^T   [4096, 2048]
    sgemm_nt<<<dim3(DD / 64, M / 64), 256>>>(x, Wq, q_p, M, DD, DD);
    // K = x @ Wk^T   [4096, 128]
    sgemm_nt<<<dim3(HD / 64, M / 64), 256>>>(x, Wk, k_p, M, HD, DD);
    // V = x @ Wv^T   [4096, 128]
    sgemm_nt<<<dim3(HD / 64, M / 64), 256>>>(x, Wv, v_p, M, HD, DD);

    // RoPE on q (per head) and k
    {
        int npq = M * DD / 2;
        rope_kernel<<<(npq + 255) / 256, 256>>>(q_p, rcos, rsin, DD, npq);
        int npk = M * HD / 2;
        rope_kernel<<<(npk + 255) / 256, 256>>>(k_p, rcos, rsin, HD, npk);
    }

    // Causal MQA flash attention -> g_att [B,S,D] (heads concatenated)
    flash_kernel<<<dim3(SS / 32, HH, BB), 128>>>(q_p, k_p, v_p, att_p);

    // out = att @ Wo^T
    sgemm_nt<<<dim3(DD / 64, M / 64), 256>>>(att_p, Wo, out, M, DD, DD);
}